// round 13
// baseline (speedup 1.0000x reference)
#include <cuda_runtime.h>

// Problem constants
#define BB   256
#define CIN  2048
#define LL   150
#define LP   160
#define CC   256
#define HH1  8192
#define OUTN 2048

#define CL160 ((long)CC * LP)        // 40960
#define ATTS  ((long)LP * LP)        // 25600
#define CL150 ((long)CC * LL)        // 38400
#define TQ    65536L                 // per-batch stride for pvT (256x256)
#define QKS   ((long)LP * 512)       // per-batch stride for qkT (160x512=81920)

#define BMT 128
#define BNT 128
#define SKF 20
#define SMF 136

#define FC1_SPLIT 8
#define FC2_SPLIT 8
#define SMEM_BYTES  98304            // gemm5: 3 stages x (16KB A + 16KB B)

// Scratch (static device arrays — no allocation allowed; zero-initialized)
__device__ __align__(256) float g_pv  [(long)BB * CL160 + 4096];
__device__ __align__(256) float g_pvT [(long)BB * TQ];
__device__ __align__(256) float g_qkT [(long)BB * QKS + 65536];  // pad: reads overhang
__device__ __align__(256) float g_att [(long)BB * ATTS + 16384];
__device__ __align__(256) float g_ao  [(long)BB * CL150 + 64];
__device__ __align__(256) float g_h   [(long)BB * HH1];
__device__ __align__(256) float g_hp  [(long)FC1_SPLIT * BB * HH1];
__device__ __align__(256) float g_op  [(long)FC2_SPLIT * BB * OUTN];
__device__ __align__(256) float g_w1c [(long)HH1 * CL150];       // tf32 bits
__device__ __align__(256) float g_w2c [(long)OUTN * HH1];
__device__ __align__(256) float g_wqkc[(long)512 * CC];          // Wq;Wk concat
__device__ __align__(256) float g_bqk [512];

__device__ __forceinline__ unsigned f2tf32(float f) {
    unsigned u;
    asm("cvt.rna.tf32.f32 %0, %1;" : "=r"(u) : "f"(f));
    return u;
}
__device__ __forceinline__ float f2tf32f(float f) {
    return __uint_as_float(f2tf32(f));
}
__device__ __forceinline__ unsigned smem_u32(const void* p) {
    unsigned a;
    asm("{ .reg .u64 t; cvta.to.shared.u64 t, %1; cvt.u32.u64 %0, t; }"
        : "=r"(a) : "l"(p));
    return a;
}

#define CP16(dst, src)                                                         \
    asm volatile("cp.async.cg.shared.global [%0], [%1], 16;"                   \
                 :: "r"(dst), "l"(src))
#define CP_COMMIT()  asm volatile("cp.async.commit_group;" ::: "memory")
#define CP_WAIT1()   asm volatile("cp.async.wait_group 1;" ::: "memory")

#define LDSM4(r0, r1, r2, r3, addr)                                            \
    asm volatile("ldmatrix.sync.aligned.m8n8.x4.shared.b16 {%0,%1,%2,%3}, [%4];" \
                 : "=r"(r0), "=r"(r1), "=r"(r2), "=r"(r3) : "r"(addr))
#define MMA(acc, a0, a1, a2, a3, b0, b1)                                       \
    asm volatile("mma.sync.aligned.m16n8k8.row.col.f32.tf32.tf32.f32 "         \
                 "{%0,%1,%2,%3}, {%4,%5,%6,%7}, {%8,%9}, {%0,%1,%2,%3};"       \
                 : "+f"(acc[0]), "+f"(acc[1]), "+f"(acc[2]), "+f"(acc[3])      \
                 : "r"(a0), "r"(a1), "r"(a2), "r"(a3), "r"(b0), "r"(b1))

// ===========================================================================
// gemm5 — operands pre-tf32 bits, k-contiguous, K%32==0. BK=32, 3-stage
// cp.async pipeline, XOR-swizzled smem, ldmatrix consumers. (proven R10/R11)
// ===========================================================================
__global__ __launch_bounds__(256, 2) void gemm5(
    const float* __restrict__ A, const float* __restrict__ B,
    const float* __restrict__ bias, int bias_mode,
    const float* __restrict__ gamma, const float* __restrict__ resid,
    long sRb, long sRm, long sRn,
    float* __restrict__ C, int out_cvt,
    int M, int N, int K,
    long sAb, long sAm,
    long sBb, long sBn,
    long sCb, long sCm, long sCn)
{
    extern __shared__ unsigned dynsm[];

    const int b  = blockIdx.z;
    const int m0 = blockIdx.y * BMT;
    const int n0 = blockIdx.x * BNT;
    const int tid  = threadIdx.x;
    const int warp = tid >> 5;
    const int lane = tid & 31;
    const int lr   = lane >> 2;
    const int lc   = lane & 3;
    const int wq   = warp >> 2;
    const int wn   = warp & 3;

    const float* Aptr = A + (long)b * sAb;
    const float* Bptr = B + (long)b * sBb;

    long aoffw[4], boffw[4];
    unsigned adst[4];
#pragma unroll
    for (int i = 0; i < 4; i++) {
        int G = tid + i * 256;
        int m = G >> 3, g = G & 7;
        aoffw[i] = (long)(m0 + m) * sAm + g * 4;
        boffw[i] = (long)(n0 + m) * sBn + g * 4;
        adst[i]  = (unsigned)((m * 32 + ((g ^ (m & 7)) * 4)) * 4);
    }
    const unsigned smA0g = smem_u32(dynsm);
    const unsigned smB0g = smA0g + 49152;

#define ISSUE(sg)                                                              \
    {                                                                          \
        unsigned sa = smA0g + (sg) * 16384, sb = smB0g + (sg) * 16384;         \
        _Pragma("unroll")                                                      \
        for (int i2 = 0; i2 < 4; i2++) {                                       \
            CP16(sa + adst[i2], Aptr + aoffw[i2]);                             \
            CP16(sb + adst[i2], Bptr + boffw[i2]);                             \
        }                                                                      \
        Aptr += 32; Bptr += 32;                                                \
    }

    const int r7 = lane & 7;
    const int aRow = wq * 64 + r7 + ((lane >> 3) & 1) * 8;
    const int aKs  = (lane >> 4);
    const int bRow = wn * 32 + ((lane >> 4) & 1) * 8 + r7;
    const int bKs  = (lane >> 3) & 1;
    unsigned aB[4], bBv[4];
#pragma unroll
    for (int ks = 0; ks < 4; ks++) {
        aB[ks]  = smA0g + (unsigned)((aRow * 32 + (((2 * ks + aKs) ^ r7) * 4)) * 4);
        bBv[ks] = smB0g + (unsigned)((bRow * 32 + (((2 * ks + bKs) ^ r7) * 4)) * 4);
    }

    float acc[4][4][4];
#pragma unroll
    for (int mi = 0; mi < 4; mi++)
#pragma unroll
        for (int ni = 0; ni < 4; ni++)
#pragma unroll
            for (int e = 0; e < 4; e++) acc[mi][ni][e] = 0.f;

    const int T = K / 32;

    ISSUE(0); CP_COMMIT();
    ISSUE(1); CP_COMMIT();

#pragma unroll 1
    for (int t = 0; t < T; t++) {
        CP_WAIT1();
        __syncthreads();
        const int st = t % 3;
        const unsigned so = (unsigned)(st * 16384);

#pragma unroll
        for (int ks = 0; ks < 4; ks++) {
            unsigned af[4][4], bq[2][4];
#pragma unroll
            for (int mi = 0; mi < 4; mi++)
                LDSM4(af[mi][0], af[mi][1], af[mi][2], af[mi][3],
                      aB[ks] + so + mi * 2048);
#pragma unroll
            for (int p = 0; p < 2; p++)
                LDSM4(bq[p][0], bq[p][1], bq[p][2], bq[p][3],
                      bBv[ks] + so + p * 2048);
#pragma unroll
            for (int mi = 0; mi < 4; mi++) {
#pragma unroll
                for (int ni = 0; ni < 4; ni++) {
                    MMA(acc[mi][ni],
                        af[mi][0], af[mi][1], af[mi][2], af[mi][3],
                        bq[ni >> 1][(ni & 1) * 2], bq[ni >> 1][(ni & 1) * 2 + 1]);
                }
            }
        }
        if (t + 2 < T) { ISSUE((t + 2) % 3); }
        CP_COMMIT();
    }

    float gm = 1.f;
    if (gamma) gm = gamma[0];
    const bool has_resid = (resid != nullptr);

#pragma unroll
    for (int mi = 0; mi < 4; mi++) {
#pragma unroll
        for (int ni = 0; ni < 4; ni++) {
#pragma unroll
            for (int e = 0; e < 4; e++) {
                int rr = m0 + wq * 64 + mi * 16 + lr + ((e >= 2) ? 8 : 0);
                int cc = n0 + wn * 32 + ni * 8 + 2 * lc + (e & 1);
                if (rr < M && cc < N) {
                    float v = acc[mi][ni][e] * gm;
                    if (bias_mode == 1)      v += bias[rr];
                    else if (bias_mode == 2) v += bias[cc];
                    if (has_resid) v += resid[(long)b * sRb + (long)rr * sRm + (long)cc * sRn];
                    if (out_cvt) v = f2tf32f(v);
                    C[(long)b * sCb + (long)rr * sCm + (long)cc * sCn] = v;
                }
            }
        }
    }
#undef ISSUE
}

// ===========================================================================
// gemm_pv — proven: A k-fast (Wv), B n-fast + guard (x). Emits tf32 bits to
// pv[b,c,l] and pvT[b,l,c].
// ===========================================================================
__global__ __launch_bounds__(256) void gemm_pv(
    const float* __restrict__ A, const float* __restrict__ B,
    const float* __restrict__ bias,
    float* __restrict__ C,  long sCb,  long sCm,  long sCn,
    float* __restrict__ C2, long sC2b, long sC2m, long sC2n,
    int M, int N, int K,
    long sBb, long sBk)
{
    __shared__ unsigned As[2][2560];
    __shared__ unsigned Bs[2][2560];

    const int b  = blockIdx.z;
    const int m0 = blockIdx.y * BMT;
    const int n0 = blockIdx.x * BNT;
    const int tid  = threadIdx.x;
    const int warp = tid >> 5;
    const int lane = tid & 31;
    const int lr   = lane >> 2;
    const int lc   = lane & 3;
    const int wq   = warp >> 2;
    const int wn   = warp & 3;

    const float* Abase = A;
    const float* Bbase = B + (long)b * sBb;
    long aoff[2]; int sa[2];
    long boff[8]; int sb[8]; bool bok[8];
#pragma unroll
    for (int i = 0; i < 2; i++) {
        int v = tid + i * 256;
        int mm = v >> 2, kv = (v & 3) * 4;
        aoff[i] = (long)(m0 + mm) * K + kv;
        sa[i]   = mm * SKF + kv;
    }
#pragma unroll
    for (int j = 0; j < 8; j++) {
        int idx = tid + j * 256;
        int nn = idx & 127, kk = idx >> 7;
        boff[j] = (long)kk * sBk + (n0 + nn);
        sb[j]   = kk * SMF + nn;
        bok[j]  = (n0 + nn) < N;
    }

    float acc[4][4][4];
#pragma unroll
    for (int mi = 0; mi < 4; mi++)
#pragma unroll
        for (int ni = 0; ni < 4; ni++)
#pragma unroll
            for (int e = 0; e < 4; e++) acc[mi][ni][e] = 0.f;

    const int T = K / 16;
    float4 la[2];
    float  lbs[8];

#define LOAD_G()                                                               \
    {                                                                          \
        la[0] = *(const float4*)(Abase + aoff[0]);                             \
        la[1] = *(const float4*)(Abase + aoff[1]);                             \
        _Pragma("unroll")                                                      \
        for (int j = 0; j < 8; j++) lbs[j] = bok[j] ? Bbase[boff[j]] : 0.f;    \
        Abase += 16; Bbase += (long)16 * sBk;                                  \
    }
#define STORE_S(buf)                                                           \
    {                                                                          \
        _Pragma("unroll")                                                      \
        for (int i = 0; i < 2; i++) {                                          \
            uint4 u = {f2tf32(la[i].x), f2tf32(la[i].y),                       \
                       f2tf32(la[i].z), f2tf32(la[i].w)};                      \
            *(uint4*)(&As[buf][sa[i]]) = u;                                    \
        }                                                                      \
        _Pragma("unroll")                                                      \
        for (int j = 0; j < 8; j++) Bs[buf][sb[j]] = f2tf32(lbs[j]);           \
    }

    LOAD_G();
    STORE_S(0);
    __syncthreads();

#pragma unroll 1
    for (int t = 0; t < T; t++) {
        const int cur = t & 1;
        if (t + 1 < T) LOAD_G();
        const unsigned* sA = As[cur];
        const unsigned* sB = Bs[cur];
#pragma unroll
        for (int ks = 0; ks < 2; ks++) {
            const int kb = ks * 8;
            unsigned af[4][4], bf[4][2];
#pragma unroll
            for (int mi = 0; mi < 4; mi++) {
                int m = wq * 64 + mi * 16 + lr;
                af[mi][0] = sA[m * SKF + kb + lc];
                af[mi][1] = sA[(m + 8) * SKF + kb + lc];
                af[mi][2] = sA[m * SKF + kb + lc + 4];
                af[mi][3] = sA[(m + 8) * SKF + kb + lc + 4];
            }
#pragma unroll
            for (int ni = 0; ni < 4; ni++) {
                int n = wn * 32 + ni * 8 + lr;
                bf[ni][0] = sB[(kb + lc) * SMF + n];
                bf[ni][1] = sB[(kb + lc + 4) * SMF + n];
            }
#pragma unroll
            for (int mi = 0; mi < 4; mi++)
#pragma unroll
                for (int ni = 0; ni < 4; ni++)
                    MMA(acc[mi][ni], af[mi][0], af[mi][1], af[mi][2], af[mi][3],
                        bf[ni][0], bf[ni][1]);
        }
        if (t + 1 < T) STORE_S(cur ^ 1);
        __syncthreads();
    }

#pragma unroll
    for (int mi = 0; mi < 4; mi++) {
#pragma unroll
        for (int ni = 0; ni < 4; ni++) {
#pragma unroll
            for (int e = 0; e < 4; e++) {
                int rr = m0 + wq * 64 + mi * 16 + lr + ((e >= 2) ? 8 : 0);
                int cc = n0 + wn * 32 + ni * 8 + 2 * lc + (e & 1);
                if (rr < M && cc < N) {
                    float v = f2tf32f(acc[mi][ni][e] + bias[rr]);
                    C [(long)b * sCb  + (long)rr * sCm  + (long)cc * sCn]  = v;
                    C2[(long)b * sC2b + (long)rr * sC2m + (long)cc * sC2n] = v;
                }
            }
        }
    }
#undef LOAD_G
#undef STORE_S
}

// Elementwise tf32-rounding (float4 vectorized, grid-stride)
__global__ __launch_bounds__(256) void cvt_tf32_kernel(
    const float4* __restrict__ in, float4* __restrict__ out, long n4)
{
    for (long i = (long)blockIdx.x * 256 + threadIdx.x; i < n4;
         i += (long)gridDim.x * 256) {
        float4 v = in[i];
        float4 o;
        o.x = f2tf32f(v.x); o.y = f2tf32f(v.y);
        o.z = f2tf32f(v.z); o.w = f2tf32f(v.w);
        out[i] = o;
    }
}

// Concat bq;bk into bqk[512]
__global__ __launch_bounds__(256) void concat_bias(
    const float* __restrict__ bq, const float* __restrict__ bk,
    float* __restrict__ bqk)
{
    int i = blockIdx.x * 256 + threadIdx.x;
    if (i < 256) bqk[i] = bq[i];
    else if (i < 512) bqk[i] = bk[i - 256];
}

// Row softmax on padded att; writes tf32-rounded probabilities.
__global__ __launch_bounds__(128) void softmax_kernel(float* __restrict__ att)
{
    __shared__ float red[32];
    const int bi = blockIdx.x / LL;
    const int li = blockIdx.x % LL;
    float* p = att + (long)bi * ATTS + (long)li * LP;
    const int tid = threadIdx.x;

    float m = -1e30f;
    for (int j = tid; j < LL; j += 128) m = fmaxf(m, p[j]);
#pragma unroll
    for (int o = 16; o > 0; o >>= 1) m = fmaxf(m, __shfl_xor_sync(0xffffffffu, m, o));
    if ((tid & 31) == 0) red[tid >> 5] = m;
    __syncthreads();
    if (tid < 32) {
        float v = (tid < 4) ? red[tid] : -1e30f;
#pragma unroll
        for (int o = 16; o > 0; o >>= 1) v = fmaxf(v, __shfl_xor_sync(0xffffffffu, v, o));
        red[tid] = v;
    }
    __syncthreads();
    m = red[0];

    float s = 0.f;
    for (int j = tid; j < LL; j += 128) {
        float e = __expf(p[j] - m);
        p[j] = e;
        s += e;
    }
#pragma unroll
    for (int o = 16; o > 0; o >>= 1) s += __shfl_xor_sync(0xffffffffu, s, o);
    __syncthreads();
    if ((tid & 31) == 0) red[tid >> 5] = s;
    __syncthreads();
    if (tid < 32) {
        float v = (tid < 4) ? red[tid] : 0.f;
#pragma unroll
        for (int o = 16; o > 0; o >>= 1) v += __shfl_xor_sync(0xffffffffu, v, o);
        red[tid] = v;
    }
    __syncthreads();
    float inv = 1.f / red[0];
    for (int j = tid; j < LL; j += 128) p[j] = f2tf32f(p[j] * inv);
}

// h = tf32(sum_z hp + b1)
__global__ __launch_bounds__(256) void reduce_fc1(
    const float* __restrict__ hp, const float* __restrict__ b1, float* __restrict__ h)
{
    long i = (long)blockIdx.x * 256 + threadIdx.x;
    const long S = (long)BB * HH1;
    float v = b1[i & (HH1 - 1)];
#pragma unroll
    for (int z = 0; z < FC1_SPLIT; z++) v += hp[i + z * S];
    h[i] = f2tf32f(v);
}

// out = sum_z op + b2
__global__ __launch_bounds__(256) void reduce_fc2(
    const float* __restrict__ op, const float* __restrict__ b2, float* __restrict__ out)
{
    long i = (long)blockIdx.x * 256 + threadIdx.x;
    const long S = (long)BB * OUTN;
    float v = b2[i & (OUTN - 1)];
#pragma unroll
    for (int z = 0; z < FC2_SPLIT; z++) v += op[i + z * S];
    out[i] = v;
}

extern "C" void kernel_launch(void* const* d_in, const int* in_sizes, int n_in,
                              void* d_out, int out_size)
{
    const float* x     = (const float*)d_in[0];
    const float* Wv    = (const float*)d_in[1];
    const float* bv    = (const float*)d_in[2];
    const float* Wq    = (const float*)d_in[3];
    const float* bq    = (const float*)d_in[4];
    const float* Wk    = (const float*)d_in[5];
    const float* bk    = (const float*)d_in[6];
    const float* gamma = (const float*)d_in[7];
    const float* W1    = (const float*)d_in[8];
    const float* b1    = (const float*)d_in[9];
    const float* W2    = (const float*)d_in[10];
    const float* b2    = (const float*)d_in[11];
    float* out = (float*)d_out;

    float *pv, *pvT, *qkT, *att, *ao, *h, *hp, *op;
    float *w1c, *w2c, *wqkc, *bqk;
    cudaGetSymbolAddress((void**)&pv,   g_pv);
    cudaGetSymbolAddress((void**)&pvT,  g_pvT);
    cudaGetSymbolAddress((void**)&qkT,  g_qkT);
    cudaGetSymbolAddress((void**)&att,  g_att);
    cudaGetSymbolAddress((void**)&ao,   g_ao);
    cudaGetSymbolAddress((void**)&h,    g_h);
    cudaGetSymbolAddress((void**)&hp,   g_hp);
    cudaGetSymbolAddress((void**)&op,   g_op);
    cudaGetSymbolAddress((void**)&w1c,  g_w1c);
    cudaGetSymbolAddress((void**)&w2c,  g_w2c);
    cudaGetSymbolAddress((void**)&wqkc, g_wqkc);
    cudaGetSymbolAddress((void**)&bqk,  g_bqk);

    static cudaStream_t s2 = nullptr;
    static cudaEvent_t evF = nullptr, evJ = nullptr;
    static int inited = 0;
    if (!inited) {
        cudaFuncSetAttribute(gemm5, cudaFuncAttributeMaxDynamicSharedMemorySize,
                             SMEM_BYTES);
        cudaStreamCreateWithFlags(&s2, cudaStreamNonBlocking);
        cudaEventCreateWithFlags(&evF, cudaEventDisableTiming);
        cudaEventCreateWithFlags(&evJ, cudaEventDisableTiming);
        inited = 1;
    }

    dim3 blk(256);

    // ---- fork: heavy weight conversions on side stream s2 ----
    cudaEventRecord(evF, 0);
    cudaStreamWaitEvent(s2, evF, 0);
    cvt_tf32_kernel<<<8192, 256, 0, s2>>>((const float4*)W1, (float4*)w1c,
                                          ((long)HH1 * CL150) / 4);
    cvt_tf32_kernel<<<4096, 256, 0, s2>>>((const float4*)W2, (float4*)w2c,
                                          ((long)OUTN * HH1) / 4);
    cudaEventRecord(evJ, s2);

    // ---- main stream: attention path ----
    cudaMemsetAsync(pv,  0, ((long)BB * CL160 + 4096) * sizeof(float));
    cudaMemsetAsync(att, 0, ((long)BB * ATTS + 16384) * sizeof(float));

    // Small converts: Wq/Wk into concatenated wqkc; bias concat
    cvt_tf32_kernel<<<64, 256>>>((const float4*)Wq, (float4*)wqkc,
                                 ((long)CC * CC) / 4);
    cvt_tf32_kernel<<<64, 256>>>((const float4*)Wk, (float4*)(wqkc + (long)CC * CC),
                                 ((long)CC * CC) / 4);
    concat_bias<<<2, 256>>>(bq, bk, bqk);

    // pv = Wv x + bv (tf32 bits); writes pv[b,c,l] and pvT[b,l,c]
    gemm_pv<<<dim3(2, 2, BB), blk>>>(
        Wv, x, bv,
        pv,  CL160, (long)LP, 1L,
        pvT, TQ,    1L,       (long)CC,
        CC, LL, CIN,
        (long)CIN * LL, (long)LL);

    // Fused q+k: qkT[b,l,c'] for c' in [0,512): rows 0-255 = q, 256-511 = k
    gemm5<<<dim3(2, 4, BB), blk, SMEM_BYTES>>>(
        wqkc, pvT, bqk, 1, nullptr, nullptr, 0, 0, 0, qkT, 1,
        512, LL, CC,
        0L, (long)CC,
        TQ, (long)CC,
        QKS, 1L, 512L);

    // energy[b,i,j] = sum_c q[b,i,c] k[b,j,c]  (A = qkT cols 0-255, B = +256)
    gemm5<<<dim3(2, 2, BB), blk, SMEM_BYTES>>>(
        qkT, qkT + 256, nullptr, 0, nullptr, nullptr, 0, 0, 0, att, 0,
        LL, LL, CC,
        QKS, 512L,
        QKS, 512L,
        ATTS, (long)LP, 1L);

    softmax_kernel<<<BB * LL, 128>>>(att);

    // ao[b,c,l] = gamma * sum_m pv[b,c,m] att[b,l,m] + pv  (K=160; pads zero)
    gemm5<<<dim3(2, 2, BB), blk, SMEM_BYTES>>>(
        pv, att, nullptr, 0, gamma, pv, CL160, (long)LP, 1L, ao, 1,
        CC, LL, LP,
        CL160, (long)LP,
        ATTS, (long)LP,
        CL150, (long)LL, 1L);

    // ---- join: weight conversions must be done before fc1/fc2 ----
    cudaStreamWaitEvent(0, evJ, 0);

    // fc1 split-K=8: hp[z] = ao_chunk @ W1c_chunk^T
    gemm5<<<dim3(HH1 / BNT, BB / BMT, FC1_SPLIT), blk, SMEM_BYTES>>>(
        ao, w1c, nullptr, 0, nullptr, nullptr, 0, 0, 0, hp, 0,
        BB, HH1, 4800,
        4800L, CL150,
        4800L, CL150,
        (long)BB * HH1, (long)HH1, 1L);

    reduce_fc1<<<(BB * HH1) / 256, 256>>>(hp, b1, h);

    // fc2 split-K=8
    gemm5<<<dim3(OUTN / BNT, BB / BMT, FC2_SPLIT), blk, SMEM_BYTES>>>(
        h, w2c, nullptr, 0, nullptr, nullptr, 0, 0, 0, op, 0,
        BB, OUTN, 1024,
        1024L, (long)HH1,
        1024L, (long)HH1,
        (long)BB * OUTN, (long)OUTN, 1L);

    reduce_fc2<<<(BB * OUTN) / 256, 256>>>(op, b2, out);
}

// round 14
// speedup vs baseline: 1.1523x; 1.1523x over previous
#include <cuda_runtime.h>

// Problem constants
#define BB   256
#define CIN  2048
#define LL   150
#define LP   160
#define CC   256
#define HH1  8192
#define OUTN 2048

#define CL160 ((long)CC * LP)        // 40960
#define ATTS  ((long)LP * LP)        // 25600
#define CL150 ((long)CC * LL)        // 38400
#define TQ    65536L                 // per-batch stride for pvT/qT/kT

#define BMT 128
#define BNT 128
#define SKF 20
#define SMF 136

#define FC1_SPLIT 8
#define FC2_SPLIT 8
#define SMEM_BYTES  98304            // gemm5: 3 stages x (16KB A + 16KB B)
#define SMEM6_BYTES 81920            // gemm6: 2 x 32KB A + 2 x 8KB B

// Scratch (static device arrays — no allocation allowed; zero-initialized)
__device__ __align__(256) float g_pv [(long)BB * CL160 + 4096];
__device__ __align__(256) float g_pvT[(long)BB * TQ];
__device__ __align__(256) float g_qT [(long)BB * TQ];
__device__ __align__(256) float g_kT [(long)BB * TQ];
__device__ __align__(256) float g_att[(long)BB * ATTS + 16384];
__device__ __align__(256) float g_ao [(long)BB * CL150 + 64];
__device__ __align__(256) float g_h  [(long)BB * HH1];
__device__ __align__(256) float g_hp [(long)FC1_SPLIT * BB * HH1];
__device__ __align__(256) float g_op [(long)FC2_SPLIT * BB * OUTN];
__device__ __align__(256) float g_wqc[(long)CC * CC];
__device__ __align__(256) float g_wkc[(long)CC * CC];

__device__ __forceinline__ unsigned f2tf32(float f) {
    unsigned u;
    asm("cvt.rna.tf32.f32 %0, %1;" : "=r"(u) : "f"(f));
    return u;
}
__device__ __forceinline__ float f2tf32f(float f) {
    return __uint_as_float(f2tf32(f));
}
__device__ __forceinline__ unsigned smem_u32(const void* p) {
    unsigned a;
    asm("{ .reg .u64 t; cvta.to.shared.u64 t, %1; cvt.u32.u64 %0, t; }"
        : "=r"(a) : "l"(p));
    return a;
}

#define CP16(dst, src)                                                         \
    asm volatile("cp.async.cg.shared.global [%0], [%1], 16;"                   \
                 :: "r"(dst), "l"(src))
#define CP_COMMIT()  asm volatile("cp.async.commit_group;" ::: "memory")
#define CP_WAIT0()   asm volatile("cp.async.wait_group 0;" ::: "memory")
#define CP_WAIT1()   asm volatile("cp.async.wait_group 1;" ::: "memory")

#define LDSM4(r0, r1, r2, r3, addr)                                            \
    asm volatile("ldmatrix.sync.aligned.m8n8.x4.shared.b16 {%0,%1,%2,%3}, [%4];" \
                 : "=r"(r0), "=r"(r1), "=r"(r2), "=r"(r3) : "r"(addr))
#define MMA(acc, a0, a1, a2, a3, b0, b1)                                       \
    asm volatile("mma.sync.aligned.m16n8k8.row.col.f32.tf32.tf32.f32 "         \
                 "{%0,%1,%2,%3}, {%4,%5,%6,%7}, {%8,%9}, {%0,%1,%2,%3};"       \
                 : "+f"(acc[0]), "+f"(acc[1]), "+f"(acc[2]), "+f"(acc[3])      \
                 : "r"(a0), "r"(a1), "r"(a2), "r"(a3), "r"(b0), "r"(b1))

// ===========================================================================
// gemm5 — operands pre-tf32 bits, k-contiguous, K%32==0. BK=32, 3-stage
// cp.async pipeline, XOR-swizzled smem, ldmatrix consumers. (proven R10/R11)
// ===========================================================================
__global__ __launch_bounds__(256, 2) void gemm5(
    const float* __restrict__ A, const float* __restrict__ B,
    const float* __restrict__ bias, int bias_mode,
    const float* __restrict__ gamma, const float* __restrict__ resid,
    long sRb, long sRm, long sRn,
    float* __restrict__ C, int out_cvt,
    int M, int N, int K,
    long sAb, long sAm,
    long sBb, long sBn,
    long sCb, long sCm, long sCn)
{
    extern __shared__ unsigned dynsm[];

    const int b  = blockIdx.z;
    const int m0 = blockIdx.y * BMT;
    const int n0 = blockIdx.x * BNT;
    const int tid  = threadIdx.x;
    const int warp = tid >> 5;
    const int lane = tid & 31;
    const int lr   = lane >> 2;
    const int lc   = lane & 3;
    const int wq   = warp >> 2;
    const int wn   = warp & 3;

    const float* Aptr = A + (long)b * sAb;
    const float* Bptr = B + (long)b * sBb;

    long aoffw[4], boffw[4];
    unsigned adst[4];
#pragma unroll
    for (int i = 0; i < 4; i++) {
        int G = tid + i * 256;
        int m = G >> 3, g = G & 7;
        aoffw[i] = (long)(m0 + m) * sAm + g * 4;
        boffw[i] = (long)(n0 + m) * sBn + g * 4;
        adst[i]  = (unsigned)((m * 32 + ((g ^ (m & 7)) * 4)) * 4);
    }
    const unsigned smA0g = smem_u32(dynsm);
    const unsigned smB0g = smA0g + 49152;

#define ISSUE(sg)                                                              \
    {                                                                          \
        unsigned sa = smA0g + (sg) * 16384, sb = smB0g + (sg) * 16384;         \
        _Pragma("unroll")                                                      \
        for (int i2 = 0; i2 < 4; i2++) {                                       \
            CP16(sa + adst[i2], Aptr + aoffw[i2]);                             \
            CP16(sb + adst[i2], Bptr + boffw[i2]);                             \
        }                                                                      \
        Aptr += 32; Bptr += 32;                                                \
    }

    const int r7 = lane & 7;
    const int aRow = wq * 64 + r7 + ((lane >> 3) & 1) * 8;
    const int aKs  = (lane >> 4);
    const int bRow = wn * 32 + ((lane >> 4) & 1) * 8 + r7;
    const int bKs  = (lane >> 3) & 1;
    unsigned aB[4], bBv[4];
#pragma unroll
    for (int ks = 0; ks < 4; ks++) {
        aB[ks]  = smA0g + (unsigned)((aRow * 32 + (((2 * ks + aKs) ^ r7) * 4)) * 4);
        bBv[ks] = smB0g + (unsigned)((bRow * 32 + (((2 * ks + bKs) ^ r7) * 4)) * 4);
    }

    float acc[4][4][4];
#pragma unroll
    for (int mi = 0; mi < 4; mi++)
#pragma unroll
        for (int ni = 0; ni < 4; ni++)
#pragma unroll
            for (int e = 0; e < 4; e++) acc[mi][ni][e] = 0.f;

    const int T = K / 32;

    ISSUE(0); CP_COMMIT();
    ISSUE(1); CP_COMMIT();

#pragma unroll 1
    for (int t = 0; t < T; t++) {
        CP_WAIT1();
        __syncthreads();
        const int st = t % 3;
        const unsigned so = (unsigned)(st * 16384);

#pragma unroll
        for (int ks = 0; ks < 4; ks++) {
            unsigned af[4][4], bq[2][4];
#pragma unroll
            for (int mi = 0; mi < 4; mi++)
                LDSM4(af[mi][0], af[mi][1], af[mi][2], af[mi][3],
                      aB[ks] + so + mi * 2048);
#pragma unroll
            for (int p = 0; p < 2; p++)
                LDSM4(bq[p][0], bq[p][1], bq[p][2], bq[p][3],
                      bBv[ks] + so + p * 2048);
#pragma unroll
            for (int mi = 0; mi < 4; mi++) {
#pragma unroll
                for (int ni = 0; ni < 4; ni++) {
                    MMA(acc[mi][ni],
                        af[mi][0], af[mi][1], af[mi][2], af[mi][3],
                        bq[ni >> 1][(ni & 1) * 2], bq[ni >> 1][(ni & 1) * 2 + 1]);
                }
            }
        }
        if (t + 2 < T) { ISSUE((t + 2) % 3); }
        CP_COMMIT();
    }

    float gm = 1.f;
    if (gamma) gm = gamma[0];
    const bool has_resid = (resid != nullptr);

#pragma unroll
    for (int mi = 0; mi < 4; mi++) {
#pragma unroll
        for (int ni = 0; ni < 4; ni++) {
#pragma unroll
            for (int e = 0; e < 4; e++) {
                int rr = m0 + wq * 64 + mi * 16 + lr + ((e >= 2) ? 8 : 0);
                int cc = n0 + wn * 32 + ni * 8 + 2 * lc + (e & 1);
                if (rr < M && cc < N) {
                    float v = acc[mi][ni][e] * gm;
                    if (bias_mode == 1)      v += bias[rr];
                    else if (bias_mode == 2) v += bias[cc];
                    if (has_resid) v += resid[(long)b * sRb + (long)rr * sRm + (long)cc * sRn];
                    if (out_cvt) v = f2tf32f(v);
                    C[(long)b * sCb + (long)rr * sCm + (long)cc * sCn] = v;
                }
            }
        }
    }
#undef ISSUE
}

// ===========================================================================
// gemm6 — fused-convert FC GEMM, occupancy-fixed. M=256 (whole batch),
// BN=64, BK=32, 80KB smem, 2 CTA/SM. A: pre-tf32 activations via 2-stage
// cp.async. B: RAW fp32 W via LDG.128 -> cvt -> swizzled STS.128 (each W
// element converted ONCE since BM spans all of M). Warp tile 64x32.
// ===========================================================================
__global__ __launch_bounds__(256, 2) void gemm6(
    const float* __restrict__ A, const float* __restrict__ Braw,
    float* __restrict__ C,
    int N, int K,                 // K = per-split chunk, %32 == 0
    long sAm, long sBn,           // full row strides
    long kChunk, long sCz)
{
    extern __shared__ unsigned dynsm[];
    // A stages: bytes [0, 65536) (2 x 32KB); B bufs: [65536, 81920) (2 x 8KB)

    const int z   = blockIdx.z;
    const int n0  = blockIdx.x * 64;
    const int tid  = threadIdx.x;
    const int warp = tid >> 5;
    const int lane = tid & 31;
    const int lr   = lane >> 2;
    const int lc   = lane & 3;
    const int wm   = warp & 3;           // m-block of 64 (4 x 64 = 256)
    const int wn   = warp >> 2;          // n-block of 32 (2 x 32 = 64)

    const float* Aptr = A + (long)z * kChunk;
    const float* Bptr = Braw + (long)z * kChunk;

    // A producer: 8 cp16/thread (256 rows x 32 k)
    long aoffw[8]; unsigned adst[8];
#pragma unroll
    for (int i = 0; i < 8; i++) {
        int G = tid + i * 256;
        int m = G >> 3, g = G & 7;
        aoffw[i] = (long)m * sAm + g * 4;
        adst[i]  = (unsigned)((m * 32 + ((g ^ (m & 7)) * 4)) * 4);
    }
    // B producer: 2 LDG.128/thread (64 rows x 32 k)
    long boffw[2]; unsigned bdst[2];
#pragma unroll
    for (int i = 0; i < 2; i++) {
        int G = tid + i * 256;
        int m = G >> 3, g = G & 7;
        boffw[i] = (long)(n0 + m) * sBn + g * 4;
        bdst[i]  = (unsigned)((m * 32 + ((g ^ (m & 7)) * 4)) * 4);
    }

    const unsigned smA0g = smem_u32(dynsm);
    const unsigned smB0g = smA0g + 65536;

    // Consumer bases (proven gemm5 formulas; wm/wn block origins)
    const int r7 = lane & 7;
    const int aRow = wm * 64 + r7 + ((lane >> 3) & 1) * 8;
    const int aKs  = (lane >> 4);
    const int bRow = wn * 32 + ((lane >> 4) & 1) * 8 + r7;
    const int bKs  = (lane >> 3) & 1;
    unsigned aB[4], bBv[4];
#pragma unroll
    for (int ks = 0; ks < 4; ks++) {
        aB[ks]  = smA0g + (unsigned)((aRow * 32 + (((2 * ks + aKs) ^ r7) * 4)) * 4);
        bBv[ks] = smB0g + (unsigned)((bRow * 32 + (((2 * ks + bKs) ^ r7) * 4)) * 4);
    }

    float acc[4][4][4];
#pragma unroll
    for (int mi = 0; mi < 4; mi++)
#pragma unroll
        for (int ni = 0; ni < 4; ni++)
#pragma unroll
            for (int e = 0; e < 4; e++) acc[mi][ni][e] = 0.f;

    const int T = K / 32;
    float4 breg[2];

#define LDGB()                                                                 \
    {                                                                          \
        breg[0] = *(const float4*)(Bptr + boffw[0]);                           \
        breg[1] = *(const float4*)(Bptr + boffw[1]);                           \
        Bptr += 32;                                                            \
    }
#define STSB(buf)                                                              \
    {                                                                          \
        char* sb = (char*)dynsm + 65536 + (buf) * 8192;                        \
        _Pragma("unroll")                                                      \
        for (int i2 = 0; i2 < 2; i2++) {                                       \
            uint4 u = {f2tf32(breg[i2].x), f2tf32(breg[i2].y),                 \
                       f2tf32(breg[i2].z), f2tf32(breg[i2].w)};                \
            *(uint4*)(sb + bdst[i2]) = u;                                      \
        }                                                                      \
    }
#define ISSUEA(sg)                                                             \
    {                                                                          \
        unsigned sa = smA0g + (sg) * 32768;                                    \
        _Pragma("unroll")                                                      \
        for (int i2 = 0; i2 < 8; i2++)                                         \
            CP16(sa + adst[i2], Aptr + aoffw[i2]);                             \
        Aptr += 32;                                                            \
    }

    // Prologue: A(0), A(1) in flight; B(0) stored; B(1) in regs.
    ISSUEA(0); CP_COMMIT();
    if (T > 1) { ISSUEA(1); CP_COMMIT(); }
    LDGB();
    STSB(0);
    if (T > 1) LDGB();

#pragma unroll 1
    for (int t = 0; t < T; t++) {
        const int cur = t & 1;
        if (t + 1 < T) CP_WAIT1(); else CP_WAIT0();
        __syncthreads();                       // A(t) + B(t) visible

        const unsigned soA = (unsigned)(cur * 32768);
        const unsigned soB = (unsigned)(cur * 8192);
#pragma unroll
        for (int ks = 0; ks < 4; ks++) {
            unsigned af[4][4], bq[2][4];
#pragma unroll
            for (int mi = 0; mi < 4; mi++)
                LDSM4(af[mi][0], af[mi][1], af[mi][2], af[mi][3],
                      aB[ks] + soA + mi * 2048);
#pragma unroll
            for (int p = 0; p < 2; p++)
                LDSM4(bq[p][0], bq[p][1], bq[p][2], bq[p][3],
                      bBv[ks] + soB + p * 2048);
#pragma unroll
            for (int mi = 0; mi < 4; mi++) {
#pragma unroll
                for (int ni = 0; ni < 4; ni++) {
                    MMA(acc[mi][ni],
                        af[mi][0], af[mi][1], af[mi][2], af[mi][3],
                        bq[ni >> 1][(ni & 1) * 2], bq[ni >> 1][(ni & 1) * 2 + 1]);
                }
            }
        }
        __syncthreads();                       // all reads of stage cur done
        if (t + 1 < T) STSB(cur ^ 1);          // B(t+1) from regs
        if (t + 2 < T) { LDGB(); ISSUEA(cur); CP_COMMIT(); }  // tile t+2
    }

#pragma unroll
    for (int mi = 0; mi < 4; mi++) {
#pragma unroll
        for (int ni = 0; ni < 4; ni++) {
#pragma unroll
            for (int e = 0; e < 4; e++) {
                int rr = wm * 64 + mi * 16 + lr + ((e >= 2) ? 8 : 0);
                int cc = n0 + wn * 32 + ni * 8 + 2 * lc + (e & 1);
                C[(long)z * sCz + (long)rr * N + cc] = acc[mi][ni][e];
            }
        }
    }
#undef LDGB
#undef STSB
#undef ISSUEA
}

// ===========================================================================
// gemm_pv — proven: A k-fast (Wv), B n-fast + guard (x). Emits tf32 bits.
// ===========================================================================
__global__ __launch_bounds__(256) void gemm_pv(
    const float* __restrict__ A, const float* __restrict__ B,
    const float* __restrict__ bias,
    float* __restrict__ C,  long sCb,  long sCm,  long sCn,
    float* __restrict__ C2, long sC2b, long sC2m, long sC2n,
    int M, int N, int K,
    long sBb, long sBk)
{
    __shared__ unsigned As[2][2560];
    __shared__ unsigned Bs[2][2560];

    const int b  = blockIdx.z;
    const int m0 = blockIdx.y * BMT;
    const int n0 = blockIdx.x * BNT;
    const int tid  = threadIdx.x;
    const int warp = tid >> 5;
    const int lane = tid & 31;
    const int lr   = lane >> 2;
    const int lc   = lane & 3;
    const int wq   = warp >> 2;
    const int wn   = warp & 3;

    const float* Abase = A;
    const float* Bbase = B + (long)b * sBb;
    long aoff[2]; int sa[2];
    long boff[8]; int sb[8]; bool bok[8];
#pragma unroll
    for (int i = 0; i < 2; i++) {
        int v = tid + i * 256;
        int mm = v >> 2, kv = (v & 3) * 4;
        aoff[i] = (long)(m0 + mm) * K + kv;
        sa[i]   = mm * SKF + kv;
    }
#pragma unroll
    for (int j = 0; j < 8; j++) {
        int idx = tid + j * 256;
        int nn = idx & 127, kk = idx >> 7;
        boff[j] = (long)kk * sBk + (n0 + nn);
        sb[j]   = kk * SMF + nn;
        bok[j]  = (n0 + nn) < N;
    }

    float acc[4][4][4];
#pragma unroll
    for (int mi = 0; mi < 4; mi++)
#pragma unroll
        for (int ni = 0; ni < 4; ni++)
#pragma unroll
            for (int e = 0; e < 4; e++) acc[mi][ni][e] = 0.f;

    const int T = K / 16;
    float4 la[2];
    float  lbs[8];

#define LOAD_G()                                                               \
    {                                                                          \
        la[0] = *(const float4*)(Abase + aoff[0]);                             \
        la[1] = *(const float4*)(Abase + aoff[1]);                             \
        _Pragma("unroll")                                                      \
        for (int j = 0; j < 8; j++) lbs[j] = bok[j] ? Bbase[boff[j]] : 0.f;    \
        Abase += 16; Bbase += (long)16 * sBk;                                  \
    }
#define STORE_S(buf)                                                           \
    {                                                                          \
        _Pragma("unroll")                                                      \
        for (int i = 0; i < 2; i++) {                                          \
            uint4 u = {f2tf32(la[i].x), f2tf32(la[i].y),                       \
                       f2tf32(la[i].z), f2tf32(la[i].w)};                      \
            *(uint4*)(&As[buf][sa[i]]) = u;                                    \
        }                                                                      \
        _Pragma("unroll")                                                      \
        for (int j = 0; j < 8; j++) Bs[buf][sb[j]] = f2tf32(lbs[j]);           \
    }

    LOAD_G();
    STORE_S(0);
    __syncthreads();

#pragma unroll 1
    for (int t = 0; t < T; t++) {
        const int cur = t & 1;
        if (t + 1 < T) LOAD_G();
        const unsigned* sA = As[cur];
        const unsigned* sB = Bs[cur];
#pragma unroll
        for (int ks = 0; ks < 2; ks++) {
            const int kb = ks * 8;
            unsigned af[4][4], bf[4][2];
#pragma unroll
            for (int mi = 0; mi < 4; mi++) {
                int m = wq * 64 + mi * 16 + lr;
                af[mi][0] = sA[m * SKF + kb + lc];
                af[mi][1] = sA[(m + 8) * SKF + kb + lc];
                af[mi][2] = sA[m * SKF + kb + lc + 4];
                af[mi][3] = sA[(m + 8) * SKF + kb + lc + 4];
            }
#pragma unroll
            for (int ni = 0; ni < 4; ni++) {
                int n = wn * 32 + ni * 8 + lr;
                bf[ni][0] = sB[(kb + lc) * SMF + n];
                bf[ni][1] = sB[(kb + lc + 4) * SMF + n];
            }
#pragma unroll
            for (int mi = 0; mi < 4; mi++)
#pragma unroll
                for (int ni = 0; ni < 4; ni++)
                    MMA(acc[mi][ni], af[mi][0], af[mi][1], af[mi][2], af[mi][3],
                        bf[ni][0], bf[ni][1]);
        }
        if (t + 1 < T) STORE_S(cur ^ 1);
        __syncthreads();
    }

#pragma unroll
    for (int mi = 0; mi < 4; mi++) {
#pragma unroll
        for (int ni = 0; ni < 4; ni++) {
#pragma unroll
            for (int e = 0; e < 4; e++) {
                int rr = m0 + wq * 64 + mi * 16 + lr + ((e >= 2) ? 8 : 0);
                int cc = n0 + wn * 32 + ni * 8 + 2 * lc + (e & 1);
                if (rr < M && cc < N) {
                    float v = f2tf32f(acc[mi][ni][e] + bias[rr]);
                    C [(long)b * sCb  + (long)rr * sCm  + (long)cc * sCn]  = v;
                    C2[(long)b * sC2b + (long)rr * sC2m + (long)cc * sC2n] = v;
                }
            }
        }
    }
#undef LOAD_G
#undef STORE_S
}

// Elementwise tf32-rounding (float4 vectorized, grid-stride)
__global__ __launch_bounds__(256) void cvt_tf32_kernel(
    const float4* __restrict__ in, float4* __restrict__ out, long n4)
{
    for (long i = (long)blockIdx.x * 256 + threadIdx.x; i < n4;
         i += (long)gridDim.x * 256) {
        float4 v = in[i];
        float4 o;
        o.x = f2tf32f(v.x); o.y = f2tf32f(v.y);
        o.z = f2tf32f(v.z); o.w = f2tf32f(v.w);
        out[i] = o;
    }
}

// Row softmax on padded att; writes tf32-rounded probabilities.
__global__ __launch_bounds__(128) void softmax_kernel(float* __restrict__ att)
{
    __shared__ float red[32];
    const int bi = blockIdx.x / LL;
    const int li = blockIdx.x % LL;
    float* p = att + (long)bi * ATTS + (long)li * LP;
    const int tid = threadIdx.x;

    float m = -1e30f;
    for (int j = tid; j < LL; j += 128) m = fmaxf(m, p[j]);
#pragma unroll
    for (int o = 16; o > 0; o >>= 1) m = fmaxf(m, __shfl_xor_sync(0xffffffffu, m, o));
    if ((tid & 31) == 0) red[tid >> 5] = m;
    __syncthreads();
    if (tid < 32) {
        float v = (tid < 4) ? red[tid] : -1e30f;
#pragma unroll
        for (int o = 16; o > 0; o >>= 1) v = fmaxf(v, __shfl_xor_sync(0xffffffffu, v, o));
        red[tid] = v;
    }
    __syncthreads();
    m = red[0];

    float s = 0.f;
    for (int j = tid; j < LL; j += 128) {
        float e = __expf(p[j] - m);
        p[j] = e;
        s += e;
    }
#pragma unroll
    for (int o = 16; o > 0; o >>= 1) s += __shfl_xor_sync(0xffffffffu, s, o);
    __syncthreads();
    if ((tid & 31) == 0) red[tid >> 5] = s;
    __syncthreads();
    if (tid < 32) {
        float v = (tid < 4) ? red[tid] : 0.f;
#pragma unroll
        for (int o = 16; o > 0; o >>= 1) v += __shfl_xor_sync(0xffffffffu, v, o);
        red[tid] = v;
    }
    __syncthreads();
    float inv = 1.f / red[0];
    for (int j = tid; j < LL; j += 128) p[j] = f2tf32f(p[j] * inv);
}

// h = tf32(sum_z hp + b1)
__global__ __launch_bounds__(256) void reduce_fc1(
    const float* __restrict__ hp, const float* __restrict__ b1, float* __restrict__ h)
{
    long i = (long)blockIdx.x * 256 + threadIdx.x;
    const long S = (long)BB * HH1;
    float v = b1[i & (HH1 - 1)];
#pragma unroll
    for (int z = 0; z < FC1_SPLIT; z++) v += hp[i + z * S];
    h[i] = f2tf32f(v);
}

// out = sum_z op + b2
__global__ __launch_bounds__(256) void reduce_fc2(
    const float* __restrict__ op, const float* __restrict__ b2, float* __restrict__ out)
{
    long i = (long)blockIdx.x * 256 + threadIdx.x;
    const long S = (long)BB * OUTN;
    float v = b2[i & (OUTN - 1)];
#pragma unroll
    for (int z = 0; z < FC2_SPLIT; z++) v += op[i + z * S];
    out[i] = v;
}

extern "C" void kernel_launch(void* const* d_in, const int* in_sizes, int n_in,
                              void* d_out, int out_size)
{
    const float* x     = (const float*)d_in[0];
    const float* Wv    = (const float*)d_in[1];
    const float* bv    = (const float*)d_in[2];
    const float* Wq    = (const float*)d_in[3];
    const float* bq    = (const float*)d_in[4];
    const float* Wk    = (const float*)d_in[5];
    const float* bk    = (const float*)d_in[6];
    const float* gamma = (const float*)d_in[7];
    const float* W1    = (const float*)d_in[8];
    const float* b1    = (const float*)d_in[9];
    const float* W2    = (const float*)d_in[10];
    const float* b2    = (const float*)d_in[11];
    float* out = (float*)d_out;

    float *pv, *pvT, *qT, *kT, *att, *ao, *h, *hp, *op, *wqc, *wkc;
    cudaGetSymbolAddress((void**)&pv,  g_pv);
    cudaGetSymbolAddress((void**)&pvT, g_pvT);
    cudaGetSymbolAddress((void**)&qT,  g_qT);
    cudaGetSymbolAddress((void**)&kT,  g_kT);
    cudaGetSymbolAddress((void**)&att, g_att);
    cudaGetSymbolAddress((void**)&ao,  g_ao);
    cudaGetSymbolAddress((void**)&h,   g_h);
    cudaGetSymbolAddress((void**)&hp,  g_hp);
    cudaGetSymbolAddress((void**)&op,  g_op);
    cudaGetSymbolAddress((void**)&wqc, g_wqc);
    cudaGetSymbolAddress((void**)&wkc, g_wkc);

    static int smem_set = 0;
    if (!smem_set) {
        cudaFuncSetAttribute(gemm5, cudaFuncAttributeMaxDynamicSharedMemorySize,
                             SMEM_BYTES);
        cudaFuncSetAttribute(gemm6, cudaFuncAttributeMaxDynamicSharedMemorySize,
                             SMEM6_BYTES);
        smem_set = 1;
    }

    dim3 blk(256);

    // Tiny weight conversions for q/k (W1/W2 are converted inside gemm6)
    cvt_tf32_kernel<<<64, 256>>>((const float4*)Wq, (float4*)wqc,
                                 ((long)CC * CC) / 4);
    cvt_tf32_kernel<<<64, 256>>>((const float4*)Wk, (float4*)wkc,
                                 ((long)CC * CC) / 4);

    // pv = Wv x + bv (tf32 bits); writes pv[b,c,l] and pvT[b,l,c]
    gemm_pv<<<dim3(2, 2, BB), blk>>>(
        Wv, x, bv,
        pv,  CL160, (long)LP, 1L,
        pvT, TQ,    1L,       (long)CC,
        CC, LL, CIN,
        (long)CIN * LL, (long)LL);

    // qT[b,l,c] = (Wq pv + bq)^T
    gemm5<<<dim3(2, 2, BB), blk, SMEM_BYTES>>>(
        wqc, pvT, bq, 1, nullptr, nullptr, 0, 0, 0, qT, 1,
        CC, LL, CC,
        0L, (long)CC,
        TQ, (long)CC,
        TQ, 1L, (long)CC);

    // kT likewise
    gemm5<<<dim3(2, 2, BB), blk, SMEM_BYTES>>>(
        wkc, pvT, bk, 1, nullptr, nullptr, 0, 0, 0, kT, 1,
        CC, LL, CC,
        0L, (long)CC,
        TQ, (long)CC,
        TQ, 1L, (long)CC);

    // energy[b,i,j] = sum_c qT[b,i,c] kT[b,j,c]
    gemm5<<<dim3(2, 2, BB), blk, SMEM_BYTES>>>(
        qT, kT, nullptr, 0, nullptr, nullptr, 0, 0, 0, att, 0,
        LL, LL, CC,
        TQ, (long)CC,
        TQ, (long)CC,
        ATTS, (long)LP, 1L);

    softmax_kernel<<<BB * LL, 128>>>(att);

    // ao[b,c,l] = gamma * sum_m pv[b,c,m] att[b,l,m] + pv
    gemm5<<<dim3(2, 2, BB), blk, SMEM_BYTES>>>(
        pv, att, nullptr, 0, gamma, pv, CL160, (long)LP, 1L, ao, 1,
        CC, LL, LP,
        CL160, (long)LP,
        ATTS, (long)LP,
        CL150, (long)LL, 1L);

    // fc1 split-K=8 with fused W1 conversion: hp[z] = ao_chunk @ W1_chunk^T
    gemm6<<<dim3(HH1 / 64, 1, FC1_SPLIT), blk, SMEM6_BYTES>>>(
        ao, W1, hp,
        HH1, 4800,
        CL150, CL150,
        4800L, (long)BB * HH1);

    reduce_fc1<<<(BB * HH1) / 256, 256>>>(hp, b1, h);

    // fc2 split-K=8 with fused W2 conversion
    gemm6<<<dim3(OUTN / 64, 1, FC2_SPLIT), blk, SMEM6_BYTES>>>(
        h, W2, op,
        OUTN, 1024,
        (long)HH1, (long)HH1,
        1024L, (long)BB * OUTN);

    reduce_fc2<<<(BB * OUTN) / 256, 256>>>(op, b2, out);
}